// round 16
// baseline (speedup 1.0000x reference)
#include <cuda_runtime.h>

// SSIM loss, single fused kernel. 4-moment formulation: blur {x,y} and {x^2+y^2, x*y}
// as two packed f32x2 channels. GMEM-direct 8-wide streamed horizontal pass with
// NO slow path (boundary handled by chunk-count specialization + run skipping),
// interleaved moment smem, 8-long vertical runs, 4 CTAs/SM.
// Shapes fixed: (16,31,256,256) fp32 x2 inputs, scalar fp32 out.

#define IMG   256
#define OUT   246          // 256 - 11 + 1
#define TW    32
#define TH    64
#define HALO  10
#define IN_H  74           // TH + HALO
#define PADI  33           // row stride (ulonglong2 elems) for interleaved moments
#define NIMG  496
#define GX    8
#define GY    4
#define NBLOCKS (GX * GY * NIMG)   // 15872
#define NTOT  30015936.0   // 496 * 246 * 246

#define SMEM_B (IN_H * PADI * 16)            // 39072  (x4 CTAs = 156 kB)

typedef unsigned long long u64;

__device__ constexpr float GW[11] = {
    0.00102838f, 0.00759874f, 0.03600078f, 0.10936071f, 0.21300555f,
    0.26601174f,
    0.21300555f, 0.10936071f, 0.03600078f, 0.00759874f, 0.00102838f
};

#define C1 1.0e-4f
#define C2 9.0e-4f

// ---- packed f32x2 helpers ----
__device__ __forceinline__ u64 pk2(float x, float y) {
    u64 r; asm("mov.b64 %0, {%1, %2};" : "=l"(r) : "f"(x), "f"(y)); return r;
}
__device__ __forceinline__ void unpk(u64 p, float& x, float& y) {
    asm("mov.b64 {%0, %1}, %2;" : "=f"(x), "=f"(y) : "l"(p));
}
__device__ __forceinline__ u64 f2fma(u64 a, u64 b, u64 c) {
    u64 d; asm("fma.rn.f32x2 %0, %1, %2, %3;" : "=l"(d) : "l"(a), "l"(b), "l"(c)); return d;
}

__device__ double   g_acc;      // zero-init; each call leaves it back at 0
__device__ unsigned g_ticket;   // wraps back to 0 every call

// 8-output horizontal run, streamed in NCHUNKS aligned float4 chunks (taps k=0..17).
// Missing chunks are zero (only ever used where the affected outputs are discarded).
// Channels: p={x,y}, q={x^2+y^2, x*y}. Live: A[8]+Q[8]=32 regs + chunk(8) + weights(12).
template<int NCHUNKS>
__device__ __forceinline__ void hrun8(const float* __restrict__ xr,
                                      const float* __restrict__ yr,
                                      bool row_ok,
                                      u64* __restrict__ A, u64* __restrict__ Q,
                                      const u64* __restrict__ W2h) {
    #pragma unroll
    for (int j = 0; j < 8; j++) { A[j] = 0; Q[j] = 0; }

    #pragma unroll
    for (int q = 0; q < NCHUNKS; q++) {
        float4 x4, y4;
        if (row_ok) {
            x4 = *(const float4*)(xr + 4 * q);
            y4 = *(const float4*)(yr + 4 * q);
        } else {
            x4 = make_float4(0.f, 0.f, 0.f, 0.f);
            y4 = make_float4(0.f, 0.f, 0.f, 0.f);
        }
        const float* xs = &x4.x;
        const float* ys = &y4.x;
        #pragma unroll
        for (int t = 0; t < 4; t++) {
            const int k = 4 * q + t;
            if (k >= 18) continue;               // static prune (k=18,19 unused)
            float xk = xs[t], yk = ys[t];
            u64   p  = pk2(xk, yk);
            float ss = fmaf(yk, yk, xk * xk);    // x^2 + y^2
            float xy = xk * yk;
            u64   qv = pk2(ss, xy);
            #pragma unroll
            for (int j = 0; j < 8; j++) {
                const int kj = k - j;
                if (kj >= 0 && kj <= 10) {
                    const int wi = (kj <= 5) ? kj : 10 - kj;   // symmetry
                    A[j] = f2fma(p,  W2h[wi], A[j]);
                    Q[j] = f2fma(qv, W2h[wi], Q[j]);
                }
            }
        }
    }
}

__global__ __launch_bounds__(256, 4)
void ssim_main_kernel(const float* __restrict__ X, const float* __restrict__ Y,
                      float* __restrict__ out) {
    extern __shared__ __align__(16) unsigned char dsm[];
    ulonglong2 (*hmi)[PADI] = (ulonglong2(*)[PADI]) dsm;  // {.x={hx,hy}, .y={hss,hxy}}
    __shared__ float red[8];

    const int tid = threadIdx.x;
    const int C0  = blockIdx.x * TW;
    const int R0  = blockIdx.y * TH;
    const int img = blockIdx.z;

    const float* __restrict__ xi = X + (size_t)img * IMG * IMG;
    const float* __restrict__ yi = Y + (size_t)img * IMG * IMG;

    // 6 distinct packed weight pairs (Gaussian symmetry: GW[k] == GW[10-k])
    u64 W2h[6];
    #pragma unroll
    for (int k = 0; k < 6; k++) W2h[k] = pk2(GW[k], GW[k]);

    // ---- Phase 1: horizontal blur from GMEM. 74 rows x 4 runs of 8 outputs = 296.
    // Boundary geometry (IMG=256, GX=8): only C0=224 can run out of columns.
    //   c0=0,8 : taps reach col C0+8+17 = 249 <= 255 -> full 5 chunks
    //   c0=16  : chunks 0..3 reach col 255; chunk 4 dropped (outputs 6,7 = cols
    //            246,247 are discarded by the oc<OUT guard in phase 2)
    //   c0=24  : all outputs >= col 248 discarded -> run skipped entirely
    //            (lanes 24..31 read uninitialized smem in phase 2, values guarded)
    const bool lastcol = (C0 == (GX - 1) * TW);
    for (int i = tid; i < IN_H * 4; i += 256) {
        const int r  = i >> 2;
        const int c0 = (i & 3) * 8;
        const int gr = R0 + r;
        const bool row_ok = (gr < IMG);
        const float* xr = xi + gr * IMG + C0 + c0;
        const float* yr = yi + gr * IMG + C0 + c0;

        u64 A[8], Q[8];
        if (lastcol) {
            if (c0 == 24) continue;
            if (c0 == 16) hrun8<4>(xr, yr, row_ok, A, Q, W2h);
            else          hrun8<5>(xr, yr, row_ok, A, Q, W2h);
        } else {
            hrun8<5>(xr, yr, row_ok, A, Q, W2h);
        }

        #pragma unroll
        for (int j = 0; j < 8; j++)
            hmi[r][c0 + j] = make_ulonglong2(A[j], Q[j]);
    }
    __syncthreads();

    // ---- Phase 2: vertical blur (streaming, 8-output runs) + SSIM.
    const int c  = tid & 31;
    const int r0 = (tid >> 5) * 8;   // 0..56

    u64 acc01[8], accq[8];
    #pragma unroll
    for (int j = 0; j < 8; j++) { acc01[j] = 0; accq[j] = 0; }

    #pragma unroll
    for (int k = 0; k < 18; k++) {
        ulonglong2 v = hmi[r0 + k][c];   // one LDS.128 feeds both packed channels
        #pragma unroll
        for (int j = 0; j < 8; j++) {
            const int kj = k - j;
            if (kj >= 0 && kj <= 10) {
                const int wi = (kj <= 5) ? kj : 10 - kj;
                acc01[j] = f2fma(v.x, W2h[wi], acc01[j]);
                accq[j]  = f2fma(v.y, W2h[wi], accq[j]);
            }
        }
    }

    float lsum = 0.f;
    const int oc = C0 + c;
    #pragma unroll
    for (int j = 0; j < 8; j++) {
        int orow = R0 + r0 + j;
        if (orow < OUT && oc < OUT) {
            float mx, my;   unpk(acc01[j], mx, my);
            float mss, mxy; unpk(accq[j],  mss, mxy);
            float mxmy = mx * my;
            float m2   = fmaf(mx, mx, my * my);          // mx^2 + my^2
            float vsum = mss - m2;                       // vx + vy
            float cov  = mxy - mxmy;
            float num  = (2.f * mxmy + C1) * (2.f * cov + C2);
            float den  = (m2 + C1) * (vsum + C2);
            lsum += __fdividef(num, den);
        }
    }

    // ---- block reduce -> global accumulator; last block finalizes + resets
    #pragma unroll
    for (int o = 16; o > 0; o >>= 1)
        lsum += __shfl_xor_sync(0xffffffffu, lsum, o);
    if ((tid & 31) == 0) red[tid >> 5] = lsum;
    __syncthreads();
    if (tid == 0) {
        float s = 0.f;
        #pragma unroll
        for (int w = 0; w < 8; w++) s += red[w];
        atomicAdd(&g_acc, (double)s);
        __threadfence();
        unsigned t = atomicInc(&g_ticket, NBLOCKS - 1);
        if (t == NBLOCKS - 1) {
            double tot = atomicAdd(&g_acc, 0.0);   // coherent read
            out[0] = (float)(1.0 - tot / NTOT);
            atomicExch((unsigned long long*)&g_acc, 0ull);  // reset for next call
        }
    }
}

extern "C" void kernel_launch(void* const* d_in, const int* in_sizes, int n_in,
                              void* d_out, int out_size) {
    const float* X = (const float*)d_in[0];
    const float* Y = (const float*)d_in[1];
    float* out = (float*)d_out;

    cudaFuncSetAttribute(ssim_main_kernel,
                         cudaFuncAttributeMaxDynamicSharedMemorySize, SMEM_B);

    dim3 grid(GX, GY, NIMG);   // 8 x 4 x 496
    ssim_main_kernel<<<grid, 256, SMEM_B>>>(X, Y, out);
}

// round 17
// speedup vs baseline: 1.2072x; 1.2072x over previous
#include <cuda_runtime.h>

// SSIM loss, single fused kernel. 4-moment formulation: blur {x,y} and {x^2+y^2, x*y}
// as two packed f32x2 channels. GMEM-direct 4-wide streamed horizontal pass.
// Moments stored in smem as f16x2 pairs (8B/pixel); all arithmetic fp32.
// Shapes fixed: (16,31,256,256) fp32 x2 inputs, scalar fp32 out.

#define IMG   256
#define OUT   246          // 256 - 11 + 1
#define TW    32
#define TH    64
#define HALO  10
#define IN_H  74           // TH + HALO
#define PADH2 34           // row stride (uint2 elems) for f16 moment array (272B, 16B-aligned)
#define NIMG  496
#define GX    8
#define GY    4
#define NBLOCKS (GX * GY * NIMG)   // 15872
#define NTOT  30015936.0   // 496 * 246 * 246

#define SMEM_B (IN_H * PADH2 * 8)            // 20128  (x4 CTAs = 80.5 kB)

typedef unsigned long long u64;
typedef unsigned int u32;

__device__ constexpr float GW[11] = {
    0.00102838f, 0.00759874f, 0.03600078f, 0.10936071f, 0.21300555f,
    0.26601174f,
    0.21300555f, 0.10936071f, 0.03600078f, 0.00759874f, 0.00102838f
};

#define C1 1.0e-4f
#define C2 9.0e-4f

// ---- packed f32x2 helpers ----
__device__ __forceinline__ u64 pk2(float x, float y) {
    u64 r; asm("mov.b64 %0, {%1, %2};" : "=l"(r) : "f"(x), "f"(y)); return r;
}
__device__ __forceinline__ void unpk(u64 p, float& x, float& y) {
    asm("mov.b64 {%0, %1}, %2;" : "=f"(x), "=f"(y) : "l"(p));
}
__device__ __forceinline__ u64 f2fma(u64 a, u64 b, u64 c) {
    u64 d; asm("fma.rn.f32x2 %0, %1, %2, %3;" : "=l"(d) : "l"(a), "l"(b), "l"(c)); return d;
}
// f32x2 (u64 pair {lo,hi}) -> f16x2 word {lo16, hi16}
__device__ __forceinline__ u32 f2x2_to_h2(u64 p) {
    float lo, hi; unpk(p, lo, hi);
    u32 r; asm("cvt.rn.f16x2.f32 %0, %1, %2;" : "=r"(r) : "f"(hi), "f"(lo));
    return r;
}
// f16x2 word -> f32x2 (u64 pair {lo,hi})
__device__ __forceinline__ u64 h2_to_f2x2(u32 h) {
    u64 r;
    asm("{\n\t"
        ".reg .b16 l, hh;\n\t"
        ".reg .f32 fl, fh;\n\t"
        "mov.b32 {l, hh}, %1;\n\t"
        "cvt.f32.f16 fl, l;\n\t"
        "cvt.f32.f16 fh, hh;\n\t"
        "mov.b64 %0, {fl, fh};\n\t"
        "}" : "=l"(r) : "r"(h));
    return r;
}

__device__ double   g_acc;      // zero-init; each call leaves it back at 0
__device__ unsigned g_ticket;   // wraps back to 0 every call

// 4-output horizontal run, streamed in 4 float4 chunks (taps k=0..13).
// Channels: p={x,y}, q={x^2+y^2, x*y}. Live: A[4]+Q[4]=16 regs + chunk(8) + weights(12).
template<bool FAST>
__device__ __forceinline__ void hrun4(const float* __restrict__ xr,
                                      const float* __restrict__ yr,
                                      int gc, bool row_ok,
                                      u64* __restrict__ A, u64* __restrict__ Q,
                                      const u64* __restrict__ W2h) {
    #pragma unroll
    for (int j = 0; j < 4; j++) { A[j] = 0; Q[j] = 0; }

    #pragma unroll
    for (int q = 0; q < 4; q++) {
        float4 x4, y4;
        if (FAST) {
            if (row_ok) {
                x4 = *(const float4*)(xr + 4 * q);
                y4 = *(const float4*)(yr + 4 * q);
            } else {
                x4 = make_float4(0.f, 0.f, 0.f, 0.f);
                y4 = make_float4(0.f, 0.f, 0.f, 0.f);
            }
        } else {
            float xt[4], yt[4];
            #pragma unroll
            for (int t = 0; t < 4; t++) {
                bool ok = row_ok && (gc + 4 * q + t < IMG);
                xt[t] = ok ? xr[4 * q + t] : 0.f;
                yt[t] = ok ? yr[4 * q + t] : 0.f;
            }
            x4 = make_float4(xt[0], xt[1], xt[2], xt[3]);
            y4 = make_float4(yt[0], yt[1], yt[2], yt[3]);
        }
        const float* xs = &x4.x;
        const float* ys = &y4.x;
        #pragma unroll
        for (int t = 0; t < 4; t++) {
            const int k = 4 * q + t;
            if (k >= 14) continue;               // static prune
            float xk = xs[t], yk = ys[t];
            u64   p  = pk2(xk, yk);
            float ss = fmaf(yk, yk, xk * xk);    // x^2 + y^2
            float xy = xk * yk;
            u64   qv = pk2(ss, xy);
            #pragma unroll
            for (int j = 0; j < 4; j++) {
                const int kj = k - j;
                if (kj >= 0 && kj <= 10) {
                    const int wi = (kj <= 5) ? kj : 10 - kj;   // symmetry
                    A[j] = f2fma(p,  W2h[wi], A[j]);
                    Q[j] = f2fma(qv, W2h[wi], Q[j]);
                }
            }
        }
    }
}

__global__ __launch_bounds__(256, 4)
void ssim_main_kernel(const float* __restrict__ X, const float* __restrict__ Y,
                      float* __restrict__ out) {
    extern __shared__ __align__(16) unsigned char dsm[];
    uint2 (*hmh)[PADH2] = (uint2(*)[PADH2]) dsm;  // per pixel: {f16x2{hx,hy}, f16x2{hss,hxy}}
    __shared__ float red[8];

    const int tid = threadIdx.x;
    const int C0  = blockIdx.x * TW;
    const int R0  = blockIdx.y * TH;
    const int img = blockIdx.z;

    const float* __restrict__ xi = X + (size_t)img * IMG * IMG;
    const float* __restrict__ yi = Y + (size_t)img * IMG * IMG;

    // 6 distinct packed weight pairs (Gaussian symmetry: GW[k] == GW[10-k])
    u64 W2h[6];
    #pragma unroll
    for (int k = 0; k < 6; k++) W2h[k] = pk2(GW[k], GW[k]);

    // ---- Phase 1: horizontal blur from GMEM. 74 rows x 8 runs of 4 outputs.
    const bool fastcol = (C0 + 43 < IMG);    // conservative in-bounds check
    for (int i = tid; i < IN_H * 8; i += 256) {
        const int r  = i >> 3;
        const int c0 = (i & 7) * 4;
        const int gr = R0 + r;
        const int gc = C0 + c0;              // multiple of 4 -> 16B aligned
        const bool row_ok = (gr < IMG);
        const float* xr = xi + gr * IMG + gc;
        const float* yr = yi + gr * IMG + gc;

        u64 A[4], Q[4];
        if (fastcol) hrun4<true >(xr, yr, gc, row_ok, A, Q, W2h);
        else         hrun4<false>(xr, yr, gc, row_ok, A, Q, W2h);

        // convert to f16x2 and store 4 pixels (32B) as two uint4
        uint4 s0, s1;
        s0.x = f2x2_to_h2(A[0]); s0.y = f2x2_to_h2(Q[0]);
        s0.z = f2x2_to_h2(A[1]); s0.w = f2x2_to_h2(Q[1]);
        s1.x = f2x2_to_h2(A[2]); s1.y = f2x2_to_h2(Q[2]);
        s1.z = f2x2_to_h2(A[3]); s1.w = f2x2_to_h2(Q[3]);
        *(uint4*)&hmh[r][c0]     = s0;
        *(uint4*)&hmh[r][c0 + 2] = s1;
    }
    __syncthreads();

    // ---- Phase 2: vertical blur (streaming, 8-output runs) + SSIM.
    const int c  = tid & 31;
    const int r0 = (tid >> 5) * 8;   // 0..56

    u64 acc01[8], accq[8];
    #pragma unroll
    for (int j = 0; j < 8; j++) { acc01[j] = 0; accq[j] = 0; }

    #pragma unroll
    for (int k = 0; k < 18; k++) {
        uint2 v = hmh[r0 + k][c];        // one LDS.64: both f16x2 channels
        u64 pa = h2_to_f2x2(v.x);        // {hx, hy} widened to f32x2
        u64 pq = h2_to_f2x2(v.y);        // {hss, hxy}
        #pragma unroll
        for (int j = 0; j < 8; j++) {
            const int kj = k - j;
            if (kj >= 0 && kj <= 10) {
                const int wi = (kj <= 5) ? kj : 10 - kj;
                acc01[j] = f2fma(pa, W2h[wi], acc01[j]);
                accq[j]  = f2fma(pq, W2h[wi], accq[j]);
            }
        }
    }

    float lsum = 0.f;
    const int oc = C0 + c;
    #pragma unroll
    for (int j = 0; j < 8; j++) {
        int orow = R0 + r0 + j;
        if (orow < OUT && oc < OUT) {
            float mx, my;   unpk(acc01[j], mx, my);
            float mss, mxy; unpk(accq[j],  mss, mxy);
            float mxmy = mx * my;
            float m2   = fmaf(mx, mx, my * my);          // mx^2 + my^2
            float vsum = mss - m2;                       // vx + vy
            float cov  = mxy - mxmy;
            float num  = (2.f * mxmy + C1) * (2.f * cov + C2);
            float den  = (m2 + C1) * (vsum + C2);
            lsum += __fdividef(num, den);
        }
    }

    // ---- block reduce -> global accumulator; last block finalizes + resets
    #pragma unroll
    for (int o = 16; o > 0; o >>= 1)
        lsum += __shfl_xor_sync(0xffffffffu, lsum, o);
    if ((tid & 31) == 0) red[tid >> 5] = lsum;
    __syncthreads();
    if (tid == 0) {
        float s = 0.f;
        #pragma unroll
        for (int w = 0; w < 8; w++) s += red[w];
        atomicAdd(&g_acc, (double)s);
        __threadfence();
        unsigned t = atomicInc(&g_ticket, NBLOCKS - 1);
        if (t == NBLOCKS - 1) {
            double tot = atomicAdd(&g_acc, 0.0);   // coherent read
            out[0] = (float)(1.0 - tot / NTOT);
            atomicExch((unsigned long long*)&g_acc, 0ull);  // reset for next call
        }
    }
}

extern "C" void kernel_launch(void* const* d_in, const int* in_sizes, int n_in,
                              void* d_out, int out_size) {
    const float* X = (const float*)d_in[0];
    const float* Y = (const float*)d_in[1];
    float* out = (float*)d_out;

    cudaFuncSetAttribute(ssim_main_kernel,
                         cudaFuncAttributeMaxDynamicSharedMemorySize, SMEM_B);

    dim3 grid(GX, GY, NIMG);   // 8 x 4 x 496
    ssim_main_kernel<<<grid, 256, SMEM_B>>>(X, Y, out);
}